// round 12
// baseline (speedup 1.0000x reference)
#include <cuda_runtime.h>
#include <cuda_bf16.h>
#include <math.h>
#include <stdint.h>

// Problem dims
#define LL    512
#define BB    2
#define DD    768
#define EDD   1536
#define NST   16
#define KCV   4
#define DTR   48
#define VV    1024
#define NTOK  (LL*BB)   // 1024 tokens, t = b*LL + l
#define NLAY  24
#define SPW   80        // DT_RANK + 2*N

// ---------------------------------------------------------------------------
// Scratch (device globals; no allocation allowed). 256B-aligned for cp.async.
// ---------------------------------------------------------------------------
__device__ __align__(256) float g_h  [NTOK*DD];
__device__ __align__(256) float g_sp [NTOK*SPW];
__device__ __align__(256) float g_dtb[NTOK*EDD];
__device__ __align__(256) float g_pin [3*NTOK*2*EDD];   // in_proj partials
__device__ __align__(256) float g_pxp [16*NTOK*SPW];    // x_proj partials
__device__ __align__(256) float g_pout[6*NTOK*DD];      // out_proj(6) / logits(4) partials

__device__ __align__(256) __nv_bfloat16 g_xnh[NTOK*DD],  g_xnl[NTOK*DD];
__device__ __align__(256) __nv_bfloat16 g_uch[NTOK*EDD], g_ucl[NTOK*EDD];
__device__ __align__(256) __nv_bfloat16 g_yh [NTOK*EDD], g_yl [NTOK*EDD];

// Converted weights (hi/lo bf16 split) + transposed fp32 dt weight
__device__ __align__(256) __nv_bfloat16 g_wih[NLAY*2*EDD*DD], g_wil[NLAY*2*EDD*DD];
__device__ __align__(256) __nv_bfloat16 g_wxh[NLAY*SPW*EDD],  g_wxl[NLAY*SPW*EDD];
__device__ __align__(256) __nv_bfloat16 g_woh[NLAY*DD*EDD],   g_wol[NLAY*DD*EDD];
__device__ __align__(256) __nv_bfloat16 g_weh[VV*DD],         g_wel[VV*DD];
__device__ __align__(256) float g_wdt[NLAY*DTR*EDD];   // dt_w transposed [lay][r][e]

// ---------------------------------------------------------------------------
// PTX helpers (arch-agnostic: cp.async / ldmatrix / mma.sync)
// ---------------------------------------------------------------------------
__device__ __forceinline__ uint32_t smem_u32(const void* p) {
    uint32_t a;
    asm("{ .reg .u64 t; cvta.to.shared.u64 t, %1; cvt.u32.u64 %0, t; }"
        : "=r"(a) : "l"(p));
    return a;
}

__device__ __forceinline__ void cp_async16(uint32_t dst, const void* src, uint32_t nbytes) {
    asm volatile("cp.async.cg.shared.global [%0], [%1], 16, %2;"
                 :: "r"(dst), "l"(src), "r"(nbytes) : "memory");
}
#define CP_COMMIT() asm volatile("cp.async.commit_group;" ::: "memory")
#define CP_WAIT1()  asm volatile("cp.async.wait_group 1;" ::: "memory")
#define CP_WAIT0()  asm volatile("cp.async.wait_group 0;" ::: "memory")

__device__ __forceinline__ void ldm_x4(uint32_t* r, uint32_t addr) {
    asm volatile("ldmatrix.sync.aligned.m8n8.x4.shared.b16 {%0,%1,%2,%3}, [%4];"
                 : "=r"(r[0]), "=r"(r[1]), "=r"(r[2]), "=r"(r[3]) : "r"(addr));
}

__device__ __forceinline__ void mma16816(float* d, const uint32_t* a, const uint32_t* b) {
    asm volatile(
        "mma.sync.aligned.m16n8k16.row.col.f32.bf16.bf16.f32 "
        "{%0,%1,%2,%3}, {%4,%5,%6,%7}, {%8,%9}, {%0,%1,%2,%3};"
        : "+f"(d[0]), "+f"(d[1]), "+f"(d[2]), "+f"(d[3])
        : "r"(a[0]), "r"(a[1]), "r"(a[2]), "r"(a[3]), "r"(b[0]), "r"(b[1]));
}

// ---------------------------------------------------------------------------
// mma.sync GEMM, bf16x3 compensated: C[M,N] = A[M,K] * W[N,K]^T (fp32-class)
// EXACT R7 configuration (proven 54us on in_proj): 128x128 CTA tile,
// K chunks of 32, 2-stage cp.async pipeline (WAIT1), 2 CTAs/SM.
// Split-K via blockIdx.z; partial z at C + z*NTOK*N.
// mode 0: store; 2: logits permute; 3: partial store (split-K).
// ---------------------------------------------------------------------------
#define TILE_B   10240            // 128 rows * 80B
#define BUF_B    (4*TILE_B)       // Ah, Al, Wh, Wl
#define GEMM_SMEM (2*BUF_B)       // 2 stages = 81920

__global__ void __launch_bounds__(256, 2) gemm_mma(
    const __nv_bfloat16* __restrict__ Ah, const __nv_bfloat16* __restrict__ Al, int lda,
    const __nv_bfloat16* __restrict__ Wh, const __nv_bfloat16* __restrict__ Wl, int ldw,
    float* __restrict__ C, int N, int K, int mode, int klen)
{
    extern __shared__ char smem[];
    const uint32_t sb = smem_u32(smem);
    const int tid  = threadIdx.x;
    const int lane = tid & 31;
    const int wid  = tid >> 5;
    const int wm   = wid & 3;        // 0..3  -> 32-row slice
    const int wn   = wid >> 2;       // 0..1  -> 64-col slice
    const int bm = blockIdx.y * 128;
    const int bn = blockIdx.x * 128;
    const int koff = blockIdx.z * klen;
    const int kend = min(koff + klen, K);
    const int nc = (kend - koff + 31) >> 5;
    if (mode == 3) C += (size_t)blockIdx.z * NTOK * N;

    float acc[2][8][4];
#pragma unroll
    for (int i = 0; i < 2; i++)
#pragma unroll
        for (int j = 0; j < 8; j++)
#pragma unroll
            for (int k = 0; k < 4; k++) acc[i][j][k] = 0.f;

    // Chunk-invariant load precompute: 8 cp.async per thread per chunk.
    const int seg = tid & 3;              // 16B segment within 64-elem row chunk
    const int r0  = tid >> 2;             // 0..63
    const __nv_bfloat16* gsrc[8];
    uint32_t dsto[8];
    bool rowok[8];
#pragma unroll
    for (int i = 0; i < 8; i++) {
        const int tile = i >> 1;
        const int row  = (i & 1) * 64 + r0;
        const __nv_bfloat16* s; int gr, ld; bool rk;
        if (tile == 0)      { s = Ah; gr = bm + row; ld = lda; rk = true; }
        else if (tile == 1) { s = Al; gr = bm + row; ld = lda; rk = true; }
        else if (tile == 2) { s = Wh; gr = bn + row; ld = ldw; rk = (bn + row) < N; }
        else                { s = Wl; gr = bn + row; ld = ldw; rk = (bn + row) < N; }
        gsrc[i]  = s + (size_t)gr * ld + koff + seg * 8;
        dsto[i]  = (uint32_t)(tile * TILE_B + row * 80 + seg * 16);
        rowok[i] = rk;
    }
    const int kseg0 = koff + seg * 8;

    auto issue = [&](int c, int buf) {
        const int kk = kseg0 + (c << 5);
        const bool kok = kk < kend;
        const uint32_t base = sb + buf * BUF_B;
#pragma unroll
        for (int i = 0; i < 8; i++) {
            bool ok = rowok[i] && kok;
            cp_async16(base + dsto[i],
                       ok ? (const void*)(gsrc[i] + (c << 5)) : (const void*)Ah,
                       ok ? 16u : 0u);
        }
    };

    issue(0, 0); CP_COMMIT();

    for (int c = 0; c < nc; c++) {
        const int buf = c & 1;
        if (c + 1 < nc) { issue(c + 1, buf ^ 1); CP_COMMIT(); CP_WAIT1(); }
        else            { CP_WAIT0(); }
        __syncthreads();

        const uint32_t bA = sb + buf * BUF_B;
        const uint32_t bW = bA + 2 * TILE_B;
        const int q = lane >> 3, l8 = lane & 7;

#pragma unroll
        for (int ks = 0; ks < 2; ks++) {
            const int k = ks << 4;
            uint32_t ah[2][4], al_[2][4];
#pragma unroll
            for (int mt = 0; mt < 2; mt++) {
                uint32_t off = (uint32_t)((wm * 32 + mt * 16 + l8 + (q & 1) * 8) * 80
                                          + (k + (q >> 1) * 8) * 2);
                ldm_x4(ah[mt],  bA + off);
                ldm_x4(al_[mt], bA + TILE_B + off);
            }
#pragma unroll
            for (int np = 0; np < 4; np++) {
                uint32_t bh4[4], bl4[4];
                uint32_t off = (uint32_t)((wn * 64 + np * 16 + l8 + (q >> 1) * 8) * 80
                                          + (k + (q & 1) * 8) * 2);
                ldm_x4(bh4, bW + off);
                ldm_x4(bl4, bW + TILE_B + off);
#pragma unroll
                for (int mt = 0; mt < 2; mt++) {
                    mma16816(acc[mt][2 * np],     ah[mt],  &bh4[0]);
                    mma16816(acc[mt][2 * np + 1], ah[mt],  &bh4[2]);
                    mma16816(acc[mt][2 * np],     ah[mt],  &bl4[0]);
                    mma16816(acc[mt][2 * np + 1], ah[mt],  &bl4[2]);
                    mma16816(acc[mt][2 * np],     al_[mt], &bh4[0]);
                    mma16816(acc[mt][2 * np + 1], al_[mt], &bh4[2]);
                }
            }
        }
        __syncthreads();
    }

    // Epilogue
    const int tr = lane >> 2, tc = (lane & 3) * 2;
#pragma unroll
    for (int mt = 0; mt < 2; mt++) {
#pragma unroll
        for (int nt = 0; nt < 8; nt++) {
            float* a4 = acc[mt][nt];
            int r0e = bm + wm * 32 + mt * 16 + tr;
            int c0 = bn + wn * 64 + nt * 8 + tc;
#pragma unroll
            for (int half = 0; half < 2; half++) {
                int row = r0e + half * 8;
                float v0 = a4[half * 2], v1 = a4[half * 2 + 1];
                if (mode == 2) {
                    int lr = row & (LL - 1), br = row >> 9;
                    size_t base = (size_t)lr * (BB * VV) + (size_t)br * VV;
                    if (c0 < N)     C[base + c0]     = v0;
                    if (c0 + 1 < N) C[base + c0 + 1] = v1;
                } else {
                    if (c0 < N)     C[(size_t)row * N + c0]     = v0;
                    if (c0 + 1 < N) C[(size_t)row * N + c0 + 1] = v1;
                }
            }
        }
    }
}

// ---------------------------------------------------------------------------
// Generic split-K reduce (final logits): sum ns partials, permute store.
// ---------------------------------------------------------------------------
__global__ void reduce_kernel(float* __restrict__ dst,
                              const float* __restrict__ part,
                              int n4, int stride4, int ns)
{
    int i = blockIdx.x * blockDim.x + threadIdx.x;
    if (i >= n4) return;
    const float4* p4 = (const float4*)part;
    float4 s = p4[i];
    for (int k = 1; k < ns; k++) {
        float4 v = p4[i + (size_t)k * stride4];
        s.x += v.x; s.y += v.y; s.z += v.z; s.w += v.w;
    }
    int idx = i << 2;
    int t = idx >> 10, v = idx & (VV - 1);
    int l = t & (LL - 1), b = t >> 9;
    ((float4*)(dst + (size_t)l * (BB * VV) + (size_t)b * VV + v))[0] = s;
}

// Fused out_proj 6-way reduce + residual + RMSNorm + bf16 split
__global__ void reduce_rms_kernel(float* __restrict__ h,
                                  const float* __restrict__ part,
                                  const float* __restrict__ w,
                                  __nv_bfloat16* __restrict__ oh,
                                  __nv_bfloat16* __restrict__ ol)
{
    const int t = blockIdx.x;
    float vals[3];
    float s = 0.f;
#pragma unroll
    for (int j = 0; j < 3; j++) {
        int i = threadIdx.x + j * 256;
        size_t o = (size_t)t * DD + i;
        float v = h[o];
#pragma unroll
        for (int k = 0; k < 6; k++) v += part[o + (size_t)k * (NTOK * DD)];
        vals[j] = v;
        h[o] = v;
        s += v * v;
    }
    __shared__ float red[256];
    red[threadIdx.x] = s;
    __syncthreads();
    for (int off = 128; off > 0; off >>= 1) {
        if (threadIdx.x < off) red[threadIdx.x] += red[threadIdx.x + off];
        __syncthreads();
    }
    float scale = rsqrtf(red[0] / (float)DD + 1e-5f);
#pragma unroll
    for (int j = 0; j < 3; j++) {
        int i = threadIdx.x + j * 256;
        float v = vals[j] * scale * w[i];
        __nv_bfloat16 hv = __float2bfloat16(v);
        oh[(size_t)t * DD + i] = hv;
        ol[(size_t)t * DD + i] = __float2bfloat16(v - __bfloat162float(hv));
    }
}

// ---------------------------------------------------------------------------
// Fused: x_proj 16-way reduce -> sp ; dt GEMM (fp32, K=48) + softplus -> dtb.
// Block = 256 threads, 16 tokens. Grid = NTOK/16 = 64.
// wt tiles [48][128] staged in smem (read ONCE per block). Thread covers
// e = e0 + (tid&15) + j*16 (j<8): smem reads broadcast across the two
// token-halves of a warp (conflict-free), dtb writes coalesced per j.
// ---------------------------------------------------------------------------
__global__ void __launch_bounds__(256) xp_dt_kernel(
    const float* __restrict__ pxp,
    float* __restrict__ sp,
    const float* __restrict__ wt,
    const float* __restrict__ dtbias,
    float* __restrict__ dtb)
{
    __shared__ float sdtr[16][DTR];
    __shared__ float swt[DTR][128];
    const int t0 = blockIdx.x * 16;
    const int tid = threadIdx.x;

    // Phase 1: 16-way partial reduce for 16 tokens x 80 cols
    for (int i = tid; i < 16 * SPW; i += 256) {
        int tok = i / SPW, col = i - tok * SPW;
        size_t off = (size_t)(t0 + tok) * SPW + col;
        float s = pxp[off];
#pragma unroll
        for (int k = 1; k < 16; k++) s += pxp[off + (size_t)k * (NTOK * SPW)];
        sp[off] = s;
        if (col < DTR) sdtr[tok][col] = s;
    }
    __syncthreads();

    // Phase 2: dt GEMM over e-tiles of 128
    const int tok  = tid >> 4;          // 0..15
    const int esub = tid & 15;          // 0..15
    for (int tile = 0; tile < EDD / 128; tile++) {
        const int e0 = tile * 128;
        for (int i = tid; i < DTR * 128; i += 256) {
            int r = i >> 7, e = i & 127;
            swt[r][e] = wt[(size_t)r * EDD + e0 + e];
        }
        __syncthreads();
        float a[8];
#pragma unroll
        for (int j = 0; j < 8; j++) a[j] = 0.f;
        const float* dr = sdtr[tok];
#pragma unroll
        for (int r = 0; r < DTR; r++) {
            float f = dr[r];
#pragma unroll
            for (int j = 0; j < 8; j++) a[j] += f * swt[r][esub + j * 16];
        }
        float* drow = dtb + (size_t)(t0 + tok) * EDD + e0;
#pragma unroll
        for (int j = 0; j < 8; j++) {
            int e = esub + j * 16;
            float x = a[j] + dtbias[e0 + e];
            drow[e] = (x > 15.f) ? x : log1pf(__expf(x));
        }
        __syncthreads();
    }
}

// dt_w transpose: [NLAY, ED, 48] -> [NLAY, 48, ED]
__global__ void dtw_transpose(const float* __restrict__ w, float* __restrict__ wt)
{
    int i = blockIdx.x * 256 + threadIdx.x;
    if (i >= NLAY * EDD * DTR) return;
    int l = i / (EDD * DTR), rem = i - l * (EDD * DTR);
    int e = rem / DTR, r = rem - e * DTR;
    wt[(size_t)l * DTR * EDD + (size_t)r * EDD + e] = w[i];
}

// ---------------------------------------------------------------------------
// Weight fp32 -> bf16 hi/lo conversion (vectorized)
// ---------------------------------------------------------------------------
__global__ void wconv_kernel(const float4* __restrict__ s,
                             __nv_bfloat162* __restrict__ h,
                             __nv_bfloat162* __restrict__ l, int n4)
{
    for (int i = blockIdx.x * blockDim.x + threadIdx.x; i < n4;
         i += gridDim.x * blockDim.x) {
        float4 v = s[i];
        __nv_bfloat16 h0 = __float2bfloat16(v.x), h1 = __float2bfloat16(v.y);
        __nv_bfloat16 h2 = __float2bfloat16(v.z), h3 = __float2bfloat16(v.w);
        h[2 * i]     = __nv_bfloat162(h0, h1);
        h[2 * i + 1] = __nv_bfloat162(h2, h3);
        l[2 * i]     = __nv_bfloat162(
            __float2bfloat16(v.x - __bfloat162float(h0)),
            __float2bfloat16(v.y - __bfloat162float(h1)));
        l[2 * i + 1] = __nv_bfloat162(
            __float2bfloat16(v.z - __bfloat162float(h2)),
            __float2bfloat16(v.w - __bfloat162float(h3)));
    }
}

// ---------------------------------------------------------------------------
// Embedding gather
// ---------------------------------------------------------------------------
__global__ void embed_kernel(const int* __restrict__ src,
                             const float* __restrict__ emb,
                             float* __restrict__ h)
{
    int t = blockIdx.x;
    int b = t >> 9, l = t & (LL - 1);
    int id = src[l * BB + b];
    const float* er = emb + (size_t)id * DD;
    float* hr = h + (size_t)t * DD;
    for (int i = threadIdx.x; i < DD; i += 256) hr[i] = er[i];
}

// ---------------------------------------------------------------------------
// RMSNorm -> bf16 hi/lo outputs (layer 0 only)
// ---------------------------------------------------------------------------
__global__ void rmsnorm2_kernel(const float* __restrict__ x,
                                const float* __restrict__ w,
                                __nv_bfloat16* __restrict__ oh,
                                __nv_bfloat16* __restrict__ ol)
{
    int t = blockIdx.x;
    const float* xr = x + (size_t)t * DD;
    float s = 0.f;
    for (int i = threadIdx.x; i < DD; i += 256) { float v = xr[i]; s += v * v; }
    __shared__ float red[256];
    red[threadIdx.x] = s;
    __syncthreads();
    for (int off = 128; off > 0; off >>= 1) {
        if (threadIdx.x < off) red[threadIdx.x] += red[threadIdx.x + off];
        __syncthreads();
    }
    float scale = rsqrtf(red[0] / (float)DD + 1e-5f);
    for (int i = threadIdx.x; i < DD; i += 256) {
        float v = xr[i] * scale * w[i];
        __nv_bfloat16 hv = __float2bfloat16(v);
        oh[(size_t)t * DD + i] = hv;
        ol[(size_t)t * DD + i] = __float2bfloat16(v - __bfloat162float(hv));
    }
}

// ---------------------------------------------------------------------------
// Depthwise causal conv (K=4) + SiLU, reading 3 split-K partials -> bf16 hi/lo
// ---------------------------------------------------------------------------
__global__ void conv_silu_kernel(const float* __restrict__ pin,
                                 const float* __restrict__ cw,
                                 const float* __restrict__ cb,
                                 __nv_bfloat16* __restrict__ uh,
                                 __nv_bfloat16* __restrict__ ul)
{
    const size_t P = (size_t)NTOK * 2 * EDD;
    int idx = blockIdx.x * blockDim.x + threadIdx.x;
    if (idx >= NTOK * EDD) return;
    int t = idx / EDD, e = idx - t * EDD;
    int l = t & (LL - 1);
    const float* base = pin + (size_t)t * (2 * EDD) + e;
    float4 w = *(const float4*)(cw + (size_t)e * KCV);
    float acc = cb[e];
#pragma unroll
    for (int tap = 0; tap < 4; tap++) {
        if (l >= 3 - tap) {
            const float* p = base - (3 - tap) * (2 * EDD);
            float v = p[0] + p[P] + p[2 * P];
            acc += v * ((const float*)&w)[tap];
        }
    }
    float s = 1.f / (1.f + __expf(-acc));
    float v = acc * s;
    __nv_bfloat16 hv = __float2bfloat16(v);
    uh[idx] = hv;
    ul[idx] = __float2bfloat16(v - __bfloat162float(hv));
}

// ---------------------------------------------------------------------------
// Selective scan: smem-staged 64-step windows, dt pre-activated, bf16 out.
// Gate read directly from the 3 in_proj partials.
// ---------------------------------------------------------------------------
__global__ void __launch_bounds__(128) scan2_kernel(
    const float* __restrict__ dtb,     // [NTOK, ED] activated
    const __nv_bfloat16* __restrict__ uch,
    const __nv_bfloat16* __restrict__ ucl,
    const float* __restrict__ sp,
    const float* __restrict__ pin,
    const float* __restrict__ A_log,
    const float* __restrict__ Dp,
    __nv_bfloat16* __restrict__ yh,
    __nv_bfloat16* __restrict__ yl)
{
    __shared__ float  sdt[64][32], suc[64][32], sg[64][32];
    __shared__ float4 sB[64][4], sC[64][4];

    const size_t P = (size_t)NTOK * 2 * EDD;
    const int b  = blockIdx.y;
    const int eb = blockIdx.x * 32;
    const int tid = threadIdx.x;
    const int q = tid & 3, er = tid >> 2;
    const int e = eb + er;

    float4 al = *(const float4*)(A_log + (size_t)e * NST + q * 4);
    float a0 = -__expf(al.x), a1 = -__expf(al.y),
          a2 = -__expf(al.z), a3 = -__expf(al.w);
    const float dD = Dp[e];

    float h0 = 0.f, h1 = 0.f, h2 = 0.f, h3 = 0.f;

    for (int w = 0; w < 8; w++) {
        const int t0 = b * LL + w * 64;
#pragma unroll
        for (int i = 0; i < 16; i++) {
            int idx = tid + i * 128;
            int s = idx >> 5, j = idx & 31;
            size_t tr = (size_t)(t0 + s);
            sdt[s][j] = dtb[tr * EDD + eb + j];
            suc[s][j] = __bfloat162float(uch[tr * EDD + eb + j])
                      + __bfloat162float(ucl[tr * EDD + eb + j]);
            const float* gp = pin + tr * (2 * EDD) + EDD + eb + j;
            sg[s][j] = gp[0] + gp[P] + gp[2 * P];
            float v = sp[tr * SPW + DTR + j];
            if (j < 16) ((float*)&sB[s][0])[j]      = v;
            else        ((float*)&sC[s][0])[j - 16] = v;
        }
        __syncthreads();
#pragma unroll 4
        for (int s = 0; s < 64; s++) {
            float dtv = sdt[s][er];
            float u = suc[s][er];
            float4 Bv = sB[s][q], Cv = sC[s][q];
            float du = dtv * u;
            h0 = __expf(dtv * a0) * h0 + du * Bv.x;
            h1 = __expf(dtv * a1) * h1 + du * Bv.y;
            h2 = __expf(dtv * a2) * h2 + du * Bv.z;
            h3 = __expf(dtv * a3) * h3 + du * Bv.w;
            float ys = h0 * Cv.x + h1 * Cv.y + h2 * Cv.z + h3 * Cv.w;
            ys += __shfl_xor_sync(0xffffffffu, ys, 1);
            ys += __shfl_xor_sync(0xffffffffu, ys, 2);
            if (q == 0) {
                float gv = sg[s][er];
                float yv = (ys + u * dD) * (gv / (1.f + __expf(-gv)));
                __nv_bfloat16 hv = __float2bfloat16(yv);
                size_t o = (size_t)(t0 + s) * EDD + e;
                yh[o] = hv;
                yl[o] = __float2bfloat16(yv - __bfloat162float(hv));
            }
        }
        __syncthreads();
    }
}

// ---------------------------------------------------------------------------
extern "C" void kernel_launch(void* const* d_in, const int* in_sizes, int n_in,
                              void* d_out, int out_size)
{
    const int*   src     = (const int*)  d_in[0];
    const float* emb     = (const float*)d_in[1];
    const float* norm_w  = (const float*)d_in[2];
    const float* in_proj = (const float*)d_in[3];
    const float* conv_w  = (const float*)d_in[4];
    const float* conv_b  = (const float*)d_in[5];
    const float* x_proj  = (const float*)d_in[6];
    const float* dt_w    = (const float*)d_in[7];
    const float* dt_b    = (const float*)d_in[8];
    const float* A_log   = (const float*)d_in[9];
    const float* Dp      = (const float*)d_in[10];
    const float* out_prj = (const float*)d_in[11];
    const float* normf_w = (const float*)d_in[12];
    float* out = (float*)d_out;
    (void)in_sizes; (void)n_in; (void)out_size;

    cudaFuncSetAttribute(gemm_mma,
                         cudaFuncAttributeMaxDynamicSharedMemorySize, GEMM_SMEM);

    float *h, *sp, *dtb, *pin, *pxp, *pout, *wdt;
    __nv_bfloat16 *xnh, *xnl, *uch, *ucl, *yh, *yl;
    __nv_bfloat16 *wih, *wil, *wxh, *wxl, *woh, *wol, *weh, *wel;
    cudaGetSymbolAddress((void**)&h,    g_h);
    cudaGetSymbolAddress((void**)&sp,   g_sp);
    cudaGetSymbolAddress((void**)&dtb,  g_dtb);
    cudaGetSymbolAddress((void**)&pin,  g_pin);
    cudaGetSymbolAddress((void**)&pxp,  g_pxp);
    cudaGetSymbolAddress((void**)&pout, g_pout);
    cudaGetSymbolAddress((void**)&wdt,  g_wdt);
    cudaGetSymbolAddress((void**)&xnh, g_xnh);
    cudaGetSymbolAddress((void**)&xnl, g_xnl);
    cudaGetSymbolAddress((void**)&uch, g_uch);
    cudaGetSymbolAddress((void**)&ucl, g_ucl);
    cudaGetSymbolAddress((void**)&yh,  g_yh);
    cudaGetSymbolAddress((void**)&yl,  g_yl);
    cudaGetSymbolAddress((void**)&wih, g_wih);
    cudaGetSymbolAddress((void**)&wil, g_wil);
    cudaGetSymbolAddress((void**)&wxh, g_wxh);
    cudaGetSymbolAddress((void**)&wxl, g_wxl);
    cudaGetSymbolAddress((void**)&woh, g_woh);
    cudaGetSymbolAddress((void**)&wol, g_wol);
    cudaGetSymbolAddress((void**)&weh, g_weh);
    cudaGetSymbolAddress((void**)&wel, g_wel);

    const dim3 gIn (2 * EDD / 128, NTOK / 128, 3);   // (24,8,3) N=3072, klen 256
    const dim3 gXp (1,             NTOK / 128, 16);  // (1,8,16) N=80,   klen 96
    const dim3 gOut(DD / 128,      NTOK / 128, 6);   // (6,8,6)  N=768,  klen 256
    const dim3 gLog(VV / 128,      NTOK / 128, 4);   // (8,8,4)  N=1024, klen 192
    const dim3 gScan(EDD / 32, BB);

    // Launch order: my launch #4 is the in_proj GEMM (profiled by ncu -s5).
    embed_kernel<<<NTOK, 256>>>(src, emb, h);                                   // 1
    wconv_kernel<<<2048, 256>>>((const float4*)in_proj,
        (__nv_bfloat162*)wih, (__nv_bfloat162*)wil, NLAY * 2 * EDD * DD / 4);   // 2
    rmsnorm2_kernel<<<NTOK, 256>>>(h, norm_w, xnh, xnl);                        // 3

    for (int lay = 0; lay < NLAY; lay++) {
        gemm_mma<<<gIn, 256, GEMM_SMEM>>>(                                      // 4 <- profiled
            xnh, xnl, DD,
            wih + (size_t)lay * 2 * EDD * DD, wil + (size_t)lay * 2 * EDD * DD, DD,
            pin, 2 * EDD, DD, 3, 256);
        if (lay == 0) {
            wconv_kernel<<<1024, 256>>>((const float4*)x_proj,
                (__nv_bfloat162*)wxh, (__nv_bfloat162*)wxl, NLAY * SPW * EDD / 4);
            dtw_transpose<<<(NLAY * EDD * DTR + 255) / 256, 256>>>(dt_w, wdt);
            wconv_kernel<<<2048, 256>>>((const float4*)out_prj,
                (__nv_bfloat162*)woh, (__nv_bfloat162*)wol, NLAY * DD * EDD / 4);
            wconv_kernel<<<1024, 256>>>((const float4*)emb,
                (__nv_bfloat162*)weh, (__nv_bfloat162*)wel, VV * DD / 4);
        }
        conv_silu_kernel<<<(NTOK * EDD) / 256, 256>>>(
            pin, conv_w + (size_t)lay * EDD * KCV, conv_b + (size_t)lay * EDD,
            uch, ucl);
        gemm_mma<<<gXp, 256, GEMM_SMEM>>>(
            uch, ucl, EDD,
            wxh + (size_t)lay * SPW * EDD, wxl + (size_t)lay * SPW * EDD, EDD,
            pxp, SPW, EDD, 3, 96);
        xp_dt_kernel<<<NTOK / 16, 256>>>(
            pxp, sp, wdt + (size_t)lay * DTR * EDD, dt_b + (size_t)lay * EDD, dtb);
        scan2_kernel<<<gScan, 128>>>(
            dtb, uch, ucl, sp, pin,
            A_log + (size_t)lay * EDD * NST, Dp + (size_t)lay * EDD, yh, yl);
        gemm_mma<<<gOut, 256, GEMM_SMEM>>>(
            yh, yl, EDD,
            woh + (size_t)lay * DD * EDD, wol + (size_t)lay * DD * EDD, EDD,
            pout, DD, EDD, 3, 256);
        reduce_rms_kernel<<<NTOK, 256>>>(
            h, pout,
            (lay + 1 < NLAY) ? (norm_w + (size_t)(lay + 1) * DD) : normf_w,
            xnh, xnl);
    }

    gemm_mma<<<gLog, 256, GEMM_SMEM>>>(
        xnh, xnl, DD, weh, wel, DD, pout, VV, DD, 3, 192);
    reduce_kernel<<<(NTOK * VV / 4 + 255) / 256, 256>>>(
        out, pout, NTOK * VV / 4, NTOK * VV / 4, 4);
}

// round 13
// speedup vs baseline: 1.2464x; 1.2464x over previous
#include <cuda_runtime.h>
#include <cuda_bf16.h>
#include <math.h>
#include <stdint.h>

// Problem dims
#define LL    512
#define BB    2
#define DD    768
#define EDD   1536
#define NST   16
#define KCV   4
#define DTR   48
#define VV    1024
#define NTOK  (LL*BB)   // 1024 tokens, t = b*LL + l
#define NLAY  24
#define SPW   80        // DT_RANK + 2*N

// ---------------------------------------------------------------------------
// Scratch (device globals; no allocation allowed). 256B-aligned for cp.async.
// ---------------------------------------------------------------------------
__device__ __align__(256) float g_h  [NTOK*DD];
__device__ __align__(256) float g_sp [NTOK*SPW];
__device__ __align__(256) float g_dtb[NTOK*EDD];
__device__ __align__(256) float g_pin [3*NTOK*2*EDD];   // in_proj partials
__device__ __align__(256) float g_pxp [16*NTOK*SPW];    // x_proj partials
__device__ __align__(256) float g_pout[3*NTOK*VV];      // out_proj / logits partials

__device__ __align__(256) __nv_bfloat16 g_xnh[NTOK*DD],  g_xnl[NTOK*DD];
__device__ __align__(256) __nv_bfloat16 g_uch[NTOK*EDD], g_ucl[NTOK*EDD];
__device__ __align__(256) __nv_bfloat16 g_dth[NTOK*DTR], g_dtl[NTOK*DTR];
__device__ __align__(256) __nv_bfloat16 g_yh [NTOK*EDD], g_yl [NTOK*EDD];

// Converted weights (hi/lo bf16 split)
__device__ __align__(256) __nv_bfloat16 g_wih[NLAY*2*EDD*DD], g_wil[NLAY*2*EDD*DD];
__device__ __align__(256) __nv_bfloat16 g_wxh[NLAY*SPW*EDD],  g_wxl[NLAY*SPW*EDD];
__device__ __align__(256) __nv_bfloat16 g_wdh[NLAY*EDD*DTR],  g_wdl[NLAY*EDD*DTR];
__device__ __align__(256) __nv_bfloat16 g_woh[NLAY*DD*EDD],   g_wol[NLAY*DD*EDD];
__device__ __align__(256) __nv_bfloat16 g_weh[VV*DD],         g_wel[VV*DD];

// ---------------------------------------------------------------------------
// PTX helpers (arch-agnostic: cp.async / ldmatrix / mma.sync)
// ---------------------------------------------------------------------------
__device__ __forceinline__ uint32_t smem_u32(const void* p) {
    uint32_t a;
    asm("{ .reg .u64 t; cvta.to.shared.u64 t, %1; cvt.u32.u64 %0, t; }"
        : "=r"(a) : "l"(p));
    return a;
}

__device__ __forceinline__ void cp_async16(uint32_t dst, const void* src, uint32_t nbytes) {
    asm volatile("cp.async.cg.shared.global [%0], [%1], 16, %2;"
                 :: "r"(dst), "l"(src), "r"(nbytes) : "memory");
}
#define CP_COMMIT() asm volatile("cp.async.commit_group;" ::: "memory")
#define CP_WAIT1()  asm volatile("cp.async.wait_group 1;" ::: "memory")
#define CP_WAIT0()  asm volatile("cp.async.wait_group 0;" ::: "memory")

__device__ __forceinline__ void ldm_x4(uint32_t* r, uint32_t addr) {
    asm volatile("ldmatrix.sync.aligned.m8n8.x4.shared.b16 {%0,%1,%2,%3}, [%4];"
                 : "=r"(r[0]), "=r"(r[1]), "=r"(r[2]), "=r"(r[3]) : "r"(addr));
}

__device__ __forceinline__ void mma16816(float* d, const uint32_t* a, const uint32_t* b) {
    asm volatile(
        "mma.sync.aligned.m16n8k16.row.col.f32.bf16.bf16.f32 "
        "{%0,%1,%2,%3}, {%4,%5,%6,%7}, {%8,%9}, {%0,%1,%2,%3};"
        : "+f"(d[0]), "+f"(d[1]), "+f"(d[2]), "+f"(d[3])
        : "r"(a[0]), "r"(a[1]), "r"(a[2]), "r"(a[3]), "r"(b[0]), "r"(b[1]));
}

__device__ __forceinline__ float softplus_f(float x) {
    return (x > 15.f) ? x : log1pf(__expf(x));
}

// ---------------------------------------------------------------------------
// mma.sync GEMM, bf16x3 compensated: C[M,N] = A[M,K] * W[N,K]^T (fp32-class)
// EXACT R7 configuration (proven 54us on in_proj): 128x128 CTA tile,
// K chunks of 32, 2-stage cp.async pipeline (WAIT1), 2 CTAs/SM.
// Split-K via blockIdx.z; partial z at C + z*NTOK*N.
// mode 0: store; 2: logits permute; 3: partial store (split-K);
// mode 4: store softplus(v + bias[col])  (dt path).
// ---------------------------------------------------------------------------
#define TILE_B   10240            // 128 rows * 80B
#define BUF_B    (4*TILE_B)       // Ah, Al, Wh, Wl
#define GEMM_SMEM (2*BUF_B)       // 2 stages = 81920

__global__ void __launch_bounds__(256, 2) gemm_mma(
    const __nv_bfloat16* __restrict__ Ah, const __nv_bfloat16* __restrict__ Al, int lda,
    const __nv_bfloat16* __restrict__ Wh, const __nv_bfloat16* __restrict__ Wl, int ldw,
    float* __restrict__ C, const float* __restrict__ bias,
    int N, int K, int mode, int klen)
{
    extern __shared__ char smem[];
    const uint32_t sb = smem_u32(smem);
    const int tid  = threadIdx.x;
    const int lane = tid & 31;
    const int wid  = tid >> 5;
    const int wm   = wid & 3;        // 0..3  -> 32-row slice
    const int wn   = wid >> 2;       // 0..1  -> 64-col slice
    const int bm = blockIdx.y * 128;
    const int bn = blockIdx.x * 128;
    const int koff = blockIdx.z * klen;
    const int kend = min(koff + klen, K);
    const int nc = (kend - koff + 31) >> 5;
    if (mode == 3) C += (size_t)blockIdx.z * NTOK * N;

    float acc[2][8][4];
#pragma unroll
    for (int i = 0; i < 2; i++)
#pragma unroll
        for (int j = 0; j < 8; j++)
#pragma unroll
            for (int k = 0; k < 4; k++) acc[i][j][k] = 0.f;

    // Chunk-invariant load precompute: 8 cp.async per thread per chunk.
    const int seg = tid & 3;              // 16B segment within 64-elem row chunk
    const int r0  = tid >> 2;             // 0..63
    const __nv_bfloat16* gsrc[8];
    uint32_t dsto[8];
    bool rowok[8];
#pragma unroll
    for (int i = 0; i < 8; i++) {
        const int tile = i >> 1;
        const int row  = (i & 1) * 64 + r0;
        const __nv_bfloat16* s; int gr, ld; bool rk;
        if (tile == 0)      { s = Ah; gr = bm + row; ld = lda; rk = true; }
        else if (tile == 1) { s = Al; gr = bm + row; ld = lda; rk = true; }
        else if (tile == 2) { s = Wh; gr = bn + row; ld = ldw; rk = (bn + row) < N; }
        else                { s = Wl; gr = bn + row; ld = ldw; rk = (bn + row) < N; }
        gsrc[i]  = s + (size_t)gr * ld + koff + seg * 8;
        dsto[i]  = (uint32_t)(tile * TILE_B + row * 80 + seg * 16);
        rowok[i] = rk;
    }
    const int kseg0 = koff + seg * 8;

    auto issue = [&](int c, int buf) {
        const int kk = kseg0 + (c << 5);
        const bool kok = kk < kend;
        const uint32_t base = sb + buf * BUF_B;
#pragma unroll
        for (int i = 0; i < 8; i++) {
            bool ok = rowok[i] && kok;
            cp_async16(base + dsto[i],
                       ok ? (const void*)(gsrc[i] + (c << 5)) : (const void*)Ah,
                       ok ? 16u : 0u);
        }
    };

    issue(0, 0); CP_COMMIT();

    for (int c = 0; c < nc; c++) {
        const int buf = c & 1;
        if (c + 1 < nc) { issue(c + 1, buf ^ 1); CP_COMMIT(); CP_WAIT1(); }
        else            { CP_WAIT0(); }
        __syncthreads();

        const uint32_t bA = sb + buf * BUF_B;
        const uint32_t bW = bA + 2 * TILE_B;
        const int q = lane >> 3, l8 = lane & 7;

#pragma unroll
        for (int ks = 0; ks < 2; ks++) {
            const int k = ks << 4;
            uint32_t ah[2][4], al_[2][4];
#pragma unroll
            for (int mt = 0; mt < 2; mt++) {
                uint32_t off = (uint32_t)((wm * 32 + mt * 16 + l8 + (q & 1) * 8) * 80
                                          + (k + (q >> 1) * 8) * 2);
                ldm_x4(ah[mt],  bA + off);
                ldm_x4(al_[mt], bA + TILE_B + off);
            }
#pragma unroll
            for (int np = 0; np < 4; np++) {
                uint32_t bh4[4], bl4[4];
                uint32_t off = (uint32_t)((wn * 64 + np * 16 + l8 + (q >> 1) * 8) * 80
                                          + (k + (q & 1) * 8) * 2);
                ldm_x4(bh4, bW + off);
                ldm_x4(bl4, bW + TILE_B + off);
#pragma unroll
                for (int mt = 0; mt < 2; mt++) {
                    mma16816(acc[mt][2 * np],     ah[mt],  &bh4[0]);
                    mma16816(acc[mt][2 * np + 1], ah[mt],  &bh4[2]);
                    mma16816(acc[mt][2 * np],     ah[mt],  &bl4[0]);
                    mma16816(acc[mt][2 * np + 1], ah[mt],  &bl4[2]);
                    mma16816(acc[mt][2 * np],     al_[mt], &bh4[0]);
                    mma16816(acc[mt][2 * np + 1], al_[mt], &bh4[2]);
                }
            }
        }
        __syncthreads();
    }

    // Epilogue
    const int tr = lane >> 2, tc = (lane & 3) * 2;
#pragma unroll
    for (int mt = 0; mt < 2; mt++) {
#pragma unroll
        for (int nt = 0; nt < 8; nt++) {
            float* a4 = acc[mt][nt];
            int r0e = bm + wm * 32 + mt * 16 + tr;
            int c0 = bn + wn * 64 + nt * 8 + tc;
#pragma unroll
            for (int half = 0; half < 2; half++) {
                int row = r0e + half * 8;
                float v0 = a4[half * 2], v1 = a4[half * 2 + 1];
                if (mode == 2) {
                    int lr = row & (LL - 1), br = row >> 9;
                    size_t base = (size_t)lr * (BB * VV) + (size_t)br * VV;
                    if (c0 < N)     C[base + c0]     = v0;
                    if (c0 + 1 < N) C[base + c0 + 1] = v1;
                } else if (mode == 4) {
                    if (c0 < N)
                        C[(size_t)row * N + c0]     = softplus_f(v0 + bias[c0]);
                    if (c0 + 1 < N)
                        C[(size_t)row * N + c0 + 1] = softplus_f(v1 + bias[c0 + 1]);
                } else {
                    if (c0 < N)     C[(size_t)row * N + c0]     = v0;
                    if (c0 + 1 < N) C[(size_t)row * N + c0 + 1] = v1;
                }
            }
        }
    }
}

// ---------------------------------------------------------------------------
// Generic split-K reduce (final logits): sum ns partials, permute store.
// ---------------------------------------------------------------------------
__global__ void reduce_kernel(float* __restrict__ dst,
                              const float* __restrict__ part,
                              int n4, int stride4, int ns)
{
    int i = blockIdx.x * blockDim.x + threadIdx.x;
    if (i >= n4) return;
    const float4* p4 = (const float4*)part;
    float4 s = p4[i];
    for (int k = 1; k < ns; k++) {
        float4 v = p4[i + (size_t)k * stride4];
        s.x += v.x; s.y += v.y; s.z += v.z; s.w += v.w;
    }
    int idx = i << 2;
    int t = idx >> 10, v = idx & (VV - 1);
    int l = t & (LL - 1), b = t >> 9;
    ((float4*)(dst + (size_t)l * (BB * VV) + (size_t)b * VV + v))[0] = s;
}

// Fused out_proj 3-way reduce + residual + RMSNorm + bf16 split
__global__ void reduce_rms_kernel(float* __restrict__ h,
                                  const float* __restrict__ part,
                                  const float* __restrict__ w,
                                  __nv_bfloat16* __restrict__ oh,
                                  __nv_bfloat16* __restrict__ ol)
{
    const int t = blockIdx.x;
    float vals[3];
    float s = 0.f;
#pragma unroll
    for (int j = 0; j < 3; j++) {
        int i = threadIdx.x + j * 256;
        size_t o = (size_t)t * DD + i;
        float v = h[o] + part[o] + part[o + (size_t)NTOK * DD]
                       + part[o + 2 * (size_t)NTOK * DD];
        vals[j] = v;
        h[o] = v;
        s += v * v;
    }
    __shared__ float red[256];
    red[threadIdx.x] = s;
    __syncthreads();
    for (int off = 128; off > 0; off >>= 1) {
        if (threadIdx.x < off) red[threadIdx.x] += red[threadIdx.x + off];
        __syncthreads();
    }
    float scale = rsqrtf(red[0] / (float)DD + 1e-5f);
#pragma unroll
    for (int j = 0; j < 3; j++) {
        int i = threadIdx.x + j * 256;
        float v = vals[j] * scale * w[i];
        __nv_bfloat16 hv = __float2bfloat16(v);
        oh[(size_t)t * DD + i] = hv;
        ol[(size_t)t * DD + i] = __float2bfloat16(v - __bfloat162float(hv));
    }
}

// xp reduce: sp[1024][80] = sum of 16 partials; also emit dt_r bf16 hi/lo.
__global__ void reduce_xp_kernel(float* __restrict__ sp,
                                 const float* __restrict__ part,
                                 __nv_bfloat16* __restrict__ dth,
                                 __nv_bfloat16* __restrict__ dtl)
{
    int i = blockIdx.x * blockDim.x + threadIdx.x;
    if (i >= NTOK * SPW) return;
    float s = part[i];
#pragma unroll
    for (int k = 1; k < 16; k++) s += part[i + k * (NTOK * SPW)];
    sp[i] = s;
    int col = i % SPW;
    if (col < DTR) {
        int t = i / SPW;
        __nv_bfloat16 hv = __float2bfloat16(s);
        dth[(size_t)t * DTR + col] = hv;
        dtl[(size_t)t * DTR + col] = __float2bfloat16(s - __bfloat162float(hv));
    }
}

// ---------------------------------------------------------------------------
// Weight fp32 -> bf16 hi/lo conversion (vectorized)
// ---------------------------------------------------------------------------
__global__ void wconv_kernel(const float4* __restrict__ s,
                             __nv_bfloat162* __restrict__ h,
                             __nv_bfloat162* __restrict__ l, int n4)
{
    for (int i = blockIdx.x * blockDim.x + threadIdx.x; i < n4;
         i += gridDim.x * blockDim.x) {
        float4 v = s[i];
        __nv_bfloat16 h0 = __float2bfloat16(v.x), h1 = __float2bfloat16(v.y);
        __nv_bfloat16 h2 = __float2bfloat16(v.z), h3 = __float2bfloat16(v.w);
        h[2 * i]     = __nv_bfloat162(h0, h1);
        h[2 * i + 1] = __nv_bfloat162(h2, h3);
        l[2 * i]     = __nv_bfloat162(
            __float2bfloat16(v.x - __bfloat162float(h0)),
            __float2bfloat16(v.y - __bfloat162float(h1)));
        l[2 * i + 1] = __nv_bfloat162(
            __float2bfloat16(v.z - __bfloat162float(h2)),
            __float2bfloat16(v.w - __bfloat162float(h3)));
    }
}

// ---------------------------------------------------------------------------
// Embedding gather
// ---------------------------------------------------------------------------
__global__ void embed_kernel(const int* __restrict__ src,
                             const float* __restrict__ emb,
                             float* __restrict__ h)
{
    int t = blockIdx.x;
    int b = t >> 9, l = t & (LL - 1);
    int id = src[l * BB + b];
    const float* er = emb + (size_t)id * DD;
    float* hr = h + (size_t)t * DD;
    for (int i = threadIdx.x; i < DD; i += 256) hr[i] = er[i];
}

// ---------------------------------------------------------------------------
// RMSNorm -> bf16 hi/lo outputs (layer 0 only)
// ---------------------------------------------------------------------------
__global__ void rmsnorm2_kernel(const float* __restrict__ x,
                                const float* __restrict__ w,
                                __nv_bfloat16* __restrict__ oh,
                                __nv_bfloat16* __restrict__ ol)
{
    int t = blockIdx.x;
    const float* xr = x + (size_t)t * DD;
    float s = 0.f;
    for (int i = threadIdx.x; i < DD; i += 256) { float v = xr[i]; s += v * v; }
    __shared__ float red[256];
    red[threadIdx.x] = s;
    __syncthreads();
    for (int off = 128; off > 0; off >>= 1) {
        if (threadIdx.x < off) red[threadIdx.x] += red[threadIdx.x + off];
        __syncthreads();
    }
    float scale = rsqrtf(red[0] / (float)DD + 1e-5f);
    for (int i = threadIdx.x; i < DD; i += 256) {
        float v = xr[i] * scale * w[i];
        __nv_bfloat16 hv = __float2bfloat16(v);
        oh[(size_t)t * DD + i] = hv;
        ol[(size_t)t * DD + i] = __float2bfloat16(v - __bfloat162float(hv));
    }
}

// ---------------------------------------------------------------------------
// Depthwise causal conv (K=4) + SiLU, float4-vectorized over 4 channels,
// reading 3 split-K partials -> bf16 hi/lo
// ---------------------------------------------------------------------------
__global__ void conv_silu_kernel(const float* __restrict__ pin,
                                 const float* __restrict__ cw,
                                 const float* __restrict__ cb,
                                 __nv_bfloat16* __restrict__ uh,
                                 __nv_bfloat16* __restrict__ ul)
{
    const size_t P = (size_t)NTOK * 2 * EDD;
    int idx4 = blockIdx.x * blockDim.x + threadIdx.x;
    if (idx4 >= NTOK * EDD / 4) return;
    int idx = idx4 << 2;
    int t = idx / EDD, e = idx - t * EDD;
    int l = t & (LL - 1);

    float4 cbv = *(const float4*)(cb + e);
    float acc[4] = {cbv.x, cbv.y, cbv.z, cbv.w};
    float4 wv[4];
#pragma unroll
    for (int j = 0; j < 4; j++) wv[j] = *(const float4*)(cw + (size_t)(e + j) * KCV);

    const float* base = pin + (size_t)t * (2 * EDD) + e;
#pragma unroll
    for (int tap = 0; tap < 4; tap++) {
        if (l >= 3 - tap) {
            const float* p = base - (3 - tap) * (2 * EDD);
            float4 a = *(const float4*)p;
            float4 b = *(const float4*)(p + P);
            float4 c = *(const float4*)(p + 2 * P);
            acc[0] += (a.x + b.x + c.x) * ((const float*)&wv[0])[tap];
            acc[1] += (a.y + b.y + c.y) * ((const float*)&wv[1])[tap];
            acc[2] += (a.z + b.z + c.z) * ((const float*)&wv[2])[tap];
            acc[3] += (a.w + b.w + c.w) * ((const float*)&wv[3])[tap];
        }
    }

    __nv_bfloat162 hp[2], lp[2];
#pragma unroll
    for (int j = 0; j < 4; j++) {
        float s = 1.f / (1.f + __expf(-acc[j]));
        float v = acc[j] * s;
        __nv_bfloat16 hv = __float2bfloat16(v);
        __nv_bfloat16 lv = __float2bfloat16(v - __bfloat162float(hv));
        if (j & 1) { hp[j >> 1].y = hv; lp[j >> 1].y = lv; }
        else       { hp[j >> 1].x = hv; lp[j >> 1].x = lv; }
    }
    *(__nv_bfloat162*)(uh + idx)     = hp[0];
    *(__nv_bfloat162*)(uh + idx + 2) = hp[1];
    *(__nv_bfloat162*)(ul + idx)     = lp[0];
    *(__nv_bfloat162*)(ul + idx + 2) = lp[1];
}

// ---------------------------------------------------------------------------
// Selective scan: smem-staged 64-step windows, dt pre-activated, bf16 out.
// Gate read directly from the 3 in_proj partials.
// ---------------------------------------------------------------------------
__global__ void __launch_bounds__(128) scan2_kernel(
    const float* __restrict__ dtb,     // [NTOK, ED] softplus-activated
    const __nv_bfloat16* __restrict__ uch,
    const __nv_bfloat16* __restrict__ ucl,
    const float* __restrict__ sp,
    const float* __restrict__ pin,
    const float* __restrict__ A_log,
    const float* __restrict__ Dp,
    __nv_bfloat16* __restrict__ yh,
    __nv_bfloat16* __restrict__ yl)
{
    __shared__ float  sdt[64][32], suc[64][32], sg[64][32];
    __shared__ float4 sB[64][4], sC[64][4];

    const size_t P = (size_t)NTOK * 2 * EDD;
    const int b  = blockIdx.y;
    const int eb = blockIdx.x * 32;
    const int tid = threadIdx.x;
    const int q = tid & 3, er = tid >> 2;
    const int e = eb + er;

    float4 al = *(const float4*)(A_log + (size_t)e * NST + q * 4);
    float a0 = -__expf(al.x), a1 = -__expf(al.y),
          a2 = -__expf(al.z), a3 = -__expf(al.w);
    const float dD = Dp[e];

    float h0 = 0.f, h1 = 0.f, h2 = 0.f, h3 = 0.f;

    for (int w = 0; w < 8; w++) {
        const int t0 = b * LL + w * 64;
#pragma unroll
        for (int i = 0; i < 16; i++) {
            int idx = tid + i * 128;
            int s = idx >> 5, j = idx & 31;
            size_t tr = (size_t)(t0 + s);
            sdt[s][j] = dtb[tr * EDD + eb + j];
            suc[s][j] = __bfloat162float(uch[tr * EDD + eb + j])
                      + __bfloat162float(ucl[tr * EDD + eb + j]);
            const float* gp = pin + tr * (2 * EDD) + EDD + eb + j;
            sg[s][j] = gp[0] + gp[P] + gp[2 * P];
            float v = sp[tr * SPW + DTR + j];
            if (j < 16) ((float*)&sB[s][0])[j]      = v;
            else        ((float*)&sC[s][0])[j - 16] = v;
        }
        __syncthreads();
#pragma unroll 4
        for (int s = 0; s < 64; s++) {
            float dtv = sdt[s][er];
            float u = suc[s][er];
            float4 Bv = sB[s][q], Cv = sC[s][q];
            float du = dtv * u;
            h0 = __expf(dtv * a0) * h0 + du * Bv.x;
            h1 = __expf(dtv * a1) * h1 + du * Bv.y;
            h2 = __expf(dtv * a2) * h2 + du * Bv.z;
            h3 = __expf(dtv * a3) * h3 + du * Bv.w;
            float ys = h0 * Cv.x + h1 * Cv.y + h2 * Cv.z + h3 * Cv.w;
            ys += __shfl_xor_sync(0xffffffffu, ys, 1);
            ys += __shfl_xor_sync(0xffffffffu, ys, 2);
            if (q == 0) {
                float gv = sg[s][er];
                float yv = (ys + u * dD) * (gv / (1.f + __expf(-gv)));
                __nv_bfloat16 hv = __float2bfloat16(yv);
                size_t o = (size_t)(t0 + s) * EDD + e;
                yh[o] = hv;
                yl[o] = __float2bfloat16(yv - __bfloat162float(hv));
            }
        }
        __syncthreads();
    }
}

// ---------------------------------------------------------------------------
extern "C" void kernel_launch(void* const* d_in, const int* in_sizes, int n_in,
                              void* d_out, int out_size)
{
    const int*   src     = (const int*)  d_in[0];
    const float* emb     = (const float*)d_in[1];
    const float* norm_w  = (const float*)d_in[2];
    const float* in_proj = (const float*)d_in[3];
    const float* conv_w  = (const float*)d_in[4];
    const float* conv_b  = (const float*)d_in[5];
    const float* x_proj  = (const float*)d_in[6];
    const float* dt_w    = (const float*)d_in[7];
    const float* dt_b    = (const float*)d_in[8];
    const float* A_log   = (const float*)d_in[9];
    const float* Dp      = (const float*)d_in[10];
    const float* out_prj = (const float*)d_in[11];
    const float* normf_w = (const float*)d_in[12];
    float* out = (float*)d_out;
    (void)in_sizes; (void)n_in; (void)out_size;

    cudaFuncSetAttribute(gemm_mma,
                         cudaFuncAttributeMaxDynamicSharedMemorySize, GEMM_SMEM);

    float *h, *sp, *dtb, *pin, *pxp, *pout;
    __nv_bfloat16 *xnh, *xnl, *uch, *ucl, *dth, *dtl, *yh, *yl;
    __nv_bfloat16 *wih, *wil, *wxh, *wxl, *wdh, *wdl, *woh, *wol, *weh, *wel;
    cudaGetSymbolAddress((void**)&h,    g_h);
    cudaGetSymbolAddress((void**)&sp,   g_sp);
    cudaGetSymbolAddress((void**)&dtb,  g_dtb);
    cudaGetSymbolAddress((void**)&pin,  g_pin);
    cudaGetSymbolAddress((void**)&pxp,  g_pxp);
    cudaGetSymbolAddress((void**)&pout, g_pout);
    cudaGetSymbolAddress((void**)&xnh, g_xnh);
    cudaGetSymbolAddress((void**)&xnl, g_xnl);
    cudaGetSymbolAddress((void**)&uch, g_uch);
    cudaGetSymbolAddress((void**)&ucl, g_ucl);
    cudaGetSymbolAddress((void**)&dth, g_dth);
    cudaGetSymbolAddress((void**)&dtl, g_dtl);
    cudaGetSymbolAddress((void**)&yh,  g_yh);
    cudaGetSymbolAddress((void**)&yl,  g_yl);
    cudaGetSymbolAddress((void**)&wih, g_wih);
    cudaGetSymbolAddress((void**)&wil, g_wil);
    cudaGetSymbolAddress((void**)&wxh, g_wxh);
    cudaGetSymbolAddress((void**)&wxl, g_wxl);
    cudaGetSymbolAddress((void**)&wdh, g_wdh);
    cudaGetSymbolAddress((void**)&wdl, g_wdl);
    cudaGetSymbolAddress((void**)&woh, g_woh);
    cudaGetSymbolAddress((void**)&wol, g_wol);
    cudaGetSymbolAddress((void**)&weh, g_weh);
    cudaGetSymbolAddress((void**)&wel, g_wel);

    const dim3 gIn (2 * EDD / 128, NTOK / 128, 3);   // N=3072, klen 256
    const dim3 gXp (1,             NTOK / 128, 16);  // N=80,   klen 96
    const dim3 gDt (EDD / 128,     NTOK / 128, 1);   // N=1536, K=48
    const dim3 gOut(DD / 128,      NTOK / 128, 3);   // N=768,  klen 512
    const dim3 gLog(VV / 128,      NTOK / 128, 2);   // N=1024, klen 384
    const dim3 gScan(EDD / 32, BB);

    // Launch order: my launch #4 is the in_proj GEMM (profiled by ncu -s5).
    embed_kernel<<<NTOK, 256>>>(src, emb, h);                                   // 1
    wconv_kernel<<<2048, 256>>>((const float4*)in_proj,
        (__nv_bfloat162*)wih, (__nv_bfloat162*)wil, NLAY * 2 * EDD * DD / 4);   // 2
    rmsnorm2_kernel<<<NTOK, 256>>>(h, norm_w, xnh, xnl);                        // 3

    for (int lay = 0; lay < NLAY; lay++) {
        gemm_mma<<<gIn, 256, GEMM_SMEM>>>(                                      // 4 <- profiled
            xnh, xnl, DD,
            wih + (size_t)lay * 2 * EDD * DD, wil + (size_t)lay * 2 * EDD * DD, DD,
            pin, (const float*)0, 2 * EDD, DD, 3, 256);
        if (lay == 0) {
            wconv_kernel<<<1024, 256>>>((const float4*)x_proj,
                (__nv_bfloat162*)wxh, (__nv_bfloat162*)wxl, NLAY * SPW * EDD / 4);
            wconv_kernel<<<1024, 256>>>((const float4*)dt_w,
                (__nv_bfloat162*)wdh, (__nv_bfloat162*)wdl, NLAY * EDD * DTR / 4);
            wconv_kernel<<<2048, 256>>>((const float4*)out_prj,
                (__nv_bfloat162*)woh, (__nv_bfloat162*)wol, NLAY * DD * EDD / 4);
            wconv_kernel<<<1024, 256>>>((const float4*)emb,
                (__nv_bfloat162*)weh, (__nv_bfloat162*)wel, VV * DD / 4);
        }
        conv_silu_kernel<<<(NTOK * EDD / 4) / 256, 256>>>(
            pin, conv_w + (size_t)lay * EDD * KCV, conv_b + (size_t)lay * EDD,
            uch, ucl);
        gemm_mma<<<gXp, 256, GEMM_SMEM>>>(
            uch, ucl, EDD,
            wxh + (size_t)lay * SPW * EDD, wxl + (size_t)lay * SPW * EDD, EDD,
            pxp, (const float*)0, SPW, EDD, 3, 96);
        reduce_xp_kernel<<<(NTOK * SPW + 255) / 256, 256>>>(sp, pxp, dth, dtl);
        gemm_mma<<<gDt, 256, GEMM_SMEM>>>(
            dth, dtl, DTR,
            wdh + (size_t)lay * EDD * DTR, wdl + (size_t)lay * EDD * DTR, DTR,
            dtb, dt_b + (size_t)lay * EDD, EDD, DTR, 4, 64);
        scan2_kernel<<<gScan, 128>>>(
            dtb, uch, ucl, sp, pin,
            A_log + (size_t)lay * EDD * NST, Dp + (size_t)lay * EDD, yh, yl);
        gemm_mma<<<gOut, 256, GEMM_SMEM>>>(
            yh, yl, EDD,
            woh + (size_t)lay * DD * EDD, wol + (size_t)lay * DD * EDD, EDD,
            pout, (const float*)0, DD, EDD, 3, 512);
        reduce_rms_kernel<<<NTOK, 256>>>(
            h, pout,
            (lay + 1 < NLAY) ? (norm_w + (size_t)(lay + 1) * DD) : normf_w,
            xnh, xnl);
    }

    gemm_mma<<<gLog, 256, GEMM_SMEM>>>(
        xnh, xnl, DD, weh, wel, DD, pout, (const float*)0, VV, DD, 3, 384);
    reduce_kernel<<<(NTOK * VV / 4 + 255) / 256, 256>>>(
        out, pout, NTOK * VV / 4, NTOK * VV / 4, 2);
}

// round 15
// speedup vs baseline: 1.2603x; 1.0112x over previous
#include <cuda_runtime.h>
#include <cuda_bf16.h>
#include <math.h>
#include <stdint.h>

// Problem dims
#define LL    512
#define BB    2
#define DD    768
#define EDD   1536
#define NST   16
#define KCV   4
#define DTR   48
#define VV    1024
#define NTOK  (LL*BB)   // 1024 tokens, t = b*LL + l
#define NLAY  24
#define SPW   80        // DT_RANK + 2*N

// PDL device-side dependency sync (no-op if no pending dependency)
#define GRID_SYNC() cudaGridDependencySynchronize()

// ---------------------------------------------------------------------------
// Scratch (device globals; no allocation allowed). 256B-aligned for cp.async.
// ---------------------------------------------------------------------------
__device__ __align__(256) float g_h  [NTOK*DD];
__device__ __align__(256) float g_sp [NTOK*SPW];
__device__ __align__(256) float g_dtb[NTOK*EDD];
__device__ __align__(256) float g_pin [3*NTOK*2*EDD];   // in_proj partials
__device__ __align__(256) float g_pxp [16*NTOK*SPW];    // x_proj partials
__device__ __align__(256) float g_pout[3*NTOK*VV];      // out_proj / logits partials

__device__ __align__(256) __nv_bfloat16 g_xnh[NTOK*DD],  g_xnl[NTOK*DD];
__device__ __align__(256) __nv_bfloat16 g_uch[NTOK*EDD], g_ucl[NTOK*EDD];
__device__ __align__(256) __nv_bfloat16 g_dth[NTOK*DTR], g_dtl[NTOK*DTR];
__device__ __align__(256) __nv_bfloat16 g_yh [NTOK*EDD], g_yl [NTOK*EDD];

// Converted weights (hi/lo bf16 split)
__device__ __align__(256) __nv_bfloat16 g_wih[NLAY*2*EDD*DD], g_wil[NLAY*2*EDD*DD];
__device__ __align__(256) __nv_bfloat16 g_wxh[NLAY*SPW*EDD],  g_wxl[NLAY*SPW*EDD];
__device__ __align__(256) __nv_bfloat16 g_wdh[NLAY*EDD*DTR],  g_wdl[NLAY*EDD*DTR];
__device__ __align__(256) __nv_bfloat16 g_woh[NLAY*DD*EDD],   g_wol[NLAY*DD*EDD];
__device__ __align__(256) __nv_bfloat16 g_weh[VV*DD],         g_wel[VV*DD];

// ---------------------------------------------------------------------------
// PTX helpers (arch-agnostic: cp.async / ldmatrix / mma.sync)
// ---------------------------------------------------------------------------
__device__ __forceinline__ uint32_t smem_u32(const void* p) {
    uint32_t a;
    asm("{ .reg .u64 t; cvta.to.shared.u64 t, %1; cvt.u32.u64 %0, t; }"
        : "=r"(a) : "l"(p));
    return a;
}

__device__ __forceinline__ void cp_async16(uint32_t dst, const void* src, uint32_t nbytes) {
    asm volatile("cp.async.cg.shared.global [%0], [%1], 16, %2;"
                 :: "r"(dst), "l"(src), "r"(nbytes) : "memory");
}
#define CP_COMMIT() asm volatile("cp.async.commit_group;" ::: "memory")
#define CP_WAIT1()  asm volatile("cp.async.wait_group 1;" ::: "memory")
#define CP_WAIT0()  asm volatile("cp.async.wait_group 0;" ::: "memory")

__device__ __forceinline__ void ldm_x4(uint32_t* r, uint32_t addr) {
    asm volatile("ldmatrix.sync.aligned.m8n8.x4.shared.b16 {%0,%1,%2,%3}, [%4];"
                 : "=r"(r[0]), "=r"(r[1]), "=r"(r[2]), "=r"(r[3]) : "r"(addr));
}

__device__ __forceinline__ void mma16816(float* d, const uint32_t* a, const uint32_t* b) {
    asm volatile(
        "mma.sync.aligned.m16n8k16.row.col.f32.bf16.bf16.f32 "
        "{%0,%1,%2,%3}, {%4,%5,%6,%7}, {%8,%9}, {%0,%1,%2,%3};"
        : "+f"(d[0]), "+f"(d[1]), "+f"(d[2]), "+f"(d[3])
        : "r"(a[0]), "r"(a[1]), "r"(a[2]), "r"(a[3]), "r"(b[0]), "r"(b[1]));
}

__device__ __forceinline__ float softplus_f(float x) {
    return (x > 15.f) ? x : log1pf(__expf(x));
}

// ---------------------------------------------------------------------------
// mma.sync GEMM, bf16x3 compensated: C[M,N] = A[M,K] * W[N,K]^T (fp32-class)
// R7/R13 configuration: 128x128 CTA tile, K chunks of 32, 2-stage cp.async
// pipeline (WAIT1), 2 CTAs/SM. Split-K via blockIdx.z.
// mode 0: store; 2: logits permute; 3: partial store; 4: softplus(v+bias).
// ---------------------------------------------------------------------------
#define TILE_B   10240            // 128 rows * 80B
#define BUF_B    (4*TILE_B)       // Ah, Al, Wh, Wl
#define GEMM_SMEM (2*BUF_B)       // 2 stages = 81920

__global__ void __launch_bounds__(256, 2) gemm_mma(
    const __nv_bfloat16* __restrict__ Ah, const __nv_bfloat16* __restrict__ Al, int lda,
    const __nv_bfloat16* __restrict__ Wh, const __nv_bfloat16* __restrict__ Wl, int ldw,
    float* __restrict__ C, const float* __restrict__ bias,
    int N, int K, int mode, int klen)
{
    GRID_SYNC();
    extern __shared__ char smem[];
    const uint32_t sb = smem_u32(smem);
    const int tid  = threadIdx.x;
    const int lane = tid & 31;
    const int wid  = tid >> 5;
    const int wm   = wid & 3;        // 0..3  -> 32-row slice
    const int wn   = wid >> 2;       // 0..1  -> 64-col slice
    const int bm = blockIdx.y * 128;
    const int bn = blockIdx.x * 128;
    const int koff = blockIdx.z * klen;
    const int kend = min(koff + klen, K);
    const int nc = (kend - koff + 31) >> 5;
    if (mode == 3) C += (size_t)blockIdx.z * NTOK * N;

    float acc[2][8][4];
#pragma unroll
    for (int i = 0; i < 2; i++)
#pragma unroll
        for (int j = 0; j < 8; j++)
#pragma unroll
            for (int k = 0; k < 4; k++) acc[i][j][k] = 0.f;

    // Chunk-invariant load precompute: 8 cp.async per thread per chunk.
    const int seg = tid & 3;              // 16B segment within 64-elem row chunk
    const int r0  = tid >> 2;             // 0..63
    const __nv_bfloat16* gsrc[8];
    uint32_t dsto[8];
    bool rowok[8];
#pragma unroll
    for (int i = 0; i < 8; i++) {
        const int tile = i >> 1;
        const int row  = (i & 1) * 64 + r0;
        const __nv_bfloat16* s; int gr, ld; bool rk;
        if (tile == 0)      { s = Ah; gr = bm + row; ld = lda; rk = true; }
        else if (tile == 1) { s = Al; gr = bm + row; ld = lda; rk = true; }
        else if (tile == 2) { s = Wh; gr = bn + row; ld = ldw; rk = (bn + row) < N; }
        else                { s = Wl; gr = bn + row; ld = ldw; rk = (bn + row) < N; }
        gsrc[i]  = s + (size_t)gr * ld + koff + seg * 8;
        dsto[i]  = (uint32_t)(tile * TILE_B + row * 80 + seg * 16);
        rowok[i] = rk;
    }
    const int kseg0 = koff + seg * 8;

    auto issue = [&](int c, int buf) {
        const int kk = kseg0 + (c << 5);
        const bool kok = kk < kend;
        const uint32_t base = sb + buf * BUF_B;
#pragma unroll
        for (int i = 0; i < 8; i++) {
            bool ok = rowok[i] && kok;
            cp_async16(base + dsto[i],
                       ok ? (const void*)(gsrc[i] + (c << 5)) : (const void*)Ah,
                       ok ? 16u : 0u);
        }
    };

    issue(0, 0); CP_COMMIT();

    for (int c = 0; c < nc; c++) {
        const int buf = c & 1;
        if (c + 1 < nc) { issue(c + 1, buf ^ 1); CP_COMMIT(); CP_WAIT1(); }
        else            { CP_WAIT0(); }
        __syncthreads();

        const uint32_t bA = sb + buf * BUF_B;
        const uint32_t bW = bA + 2 * TILE_B;
        const int q = lane >> 3, l8 = lane & 7;

#pragma unroll
        for (int ks = 0; ks < 2; ks++) {
            const int k = ks << 4;
            uint32_t ah[2][4], al_[2][4];
#pragma unroll
            for (int mt = 0; mt < 2; mt++) {
                uint32_t off = (uint32_t)((wm * 32 + mt * 16 + l8 + (q & 1) * 8) * 80
                                          + (k + (q >> 1) * 8) * 2);
                ldm_x4(ah[mt],  bA + off);
                ldm_x4(al_[mt], bA + TILE_B + off);
            }
#pragma unroll
            for (int np = 0; np < 4; np++) {
                uint32_t bh4[4], bl4[4];
                uint32_t off = (uint32_t)((wn * 64 + np * 16 + l8 + (q >> 1) * 8) * 80
                                          + (k + (q & 1) * 8) * 2);
                ldm_x4(bh4, bW + off);
                ldm_x4(bl4, bW + TILE_B + off);
#pragma unroll
                for (int mt = 0; mt < 2; mt++) {
                    mma16816(acc[mt][2 * np],     ah[mt],  &bh4[0]);
                    mma16816(acc[mt][2 * np + 1], ah[mt],  &bh4[2]);
                    mma16816(acc[mt][2 * np],     ah[mt],  &bl4[0]);
                    mma16816(acc[mt][2 * np + 1], ah[mt],  &bl4[2]);
                    mma16816(acc[mt][2 * np],     al_[mt], &bh4[0]);
                    mma16816(acc[mt][2 * np + 1], al_[mt], &bh4[2]);
                }
            }
        }
        __syncthreads();
    }

    // Epilogue
    const int tr = lane >> 2, tc = (lane & 3) * 2;
#pragma unroll
    for (int mt = 0; mt < 2; mt++) {
#pragma unroll
        for (int nt = 0; nt < 8; nt++) {
            float* a4 = acc[mt][nt];
            int r0e = bm + wm * 32 + mt * 16 + tr;
            int c0 = bn + wn * 64 + nt * 8 + tc;
#pragma unroll
            for (int half = 0; half < 2; half++) {
                int row = r0e + half * 8;
                float v0 = a4[half * 2], v1 = a4[half * 2 + 1];
                if (mode == 2) {
                    int lr = row & (LL - 1), br = row >> 9;
                    size_t base = (size_t)lr * (BB * VV) + (size_t)br * VV;
                    if (c0 < N)     C[base + c0]     = v0;
                    if (c0 + 1 < N) C[base + c0 + 1] = v1;
                } else if (mode == 4) {
                    if (c0 < N)
                        C[(size_t)row * N + c0]     = softplus_f(v0 + bias[c0]);
                    if (c0 + 1 < N)
                        C[(size_t)row * N + c0 + 1] = softplus_f(v1 + bias[c0 + 1]);
                } else {
                    if (c0 < N)     C[(size_t)row * N + c0]     = v0;
                    if (c0 + 1 < N) C[(size_t)row * N + c0 + 1] = v1;
                }
            }
        }
    }
}

// ---------------------------------------------------------------------------
// Generic split-K reduce (final logits): sum ns partials, permute store.
// ---------------------------------------------------------------------------
__global__ void reduce_kernel(float* __restrict__ dst,
                              const float* __restrict__ part,
                              int n4, int stride4, int ns)
{
    GRID_SYNC();
    int i = blockIdx.x * blockDim.x + threadIdx.x;
    if (i >= n4) return;
    const float4* p4 = (const float4*)part;
    float4 s = p4[i];
    for (int k = 1; k < ns; k++) {
        float4 v = p4[i + (size_t)k * stride4];
        s.x += v.x; s.y += v.y; s.z += v.z; s.w += v.w;
    }
    int idx = i << 2;
    int t = idx >> 10, v = idx & (VV - 1);
    int l = t & (LL - 1), b = t >> 9;
    ((float4*)(dst + (size_t)l * (BB * VV) + (size_t)b * VV + v))[0] = s;
}

// Fused out_proj 3-way reduce + residual + RMSNorm + bf16 split
__global__ void reduce_rms_kernel(float* __restrict__ h,
                                  const float* __restrict__ part,
                                  const float* __restrict__ w,
                                  __nv_bfloat16* __restrict__ oh,
                                  __nv_bfloat16* __restrict__ ol)
{
    GRID_SYNC();
    const int t = blockIdx.x;
    float vals[3];
    float s = 0.f;
#pragma unroll
    for (int j = 0; j < 3; j++) {
        int i = threadIdx.x + j * 256;
        size_t o = (size_t)t * DD + i;
        float v = h[o] + part[o] + part[o + (size_t)NTOK * DD]
                       + part[o + 2 * (size_t)NTOK * DD];
        vals[j] = v;
        h[o] = v;
        s += v * v;
    }
    __shared__ float red[256];
    red[threadIdx.x] = s;
    __syncthreads();
    for (int off = 128; off > 0; off >>= 1) {
        if (threadIdx.x < off) red[threadIdx.x] += red[threadIdx.x + off];
        __syncthreads();
    }
    float scale = rsqrtf(red[0] / (float)DD + 1e-5f);
#pragma unroll
    for (int j = 0; j < 3; j++) {
        int i = threadIdx.x + j * 256;
        float v = vals[j] * scale * w[i];
        __nv_bfloat16 hv = __float2bfloat16(v);
        oh[(size_t)t * DD + i] = hv;
        ol[(size_t)t * DD + i] = __float2bfloat16(v - __bfloat162float(hv));
    }
}

// xp reduce: sp[1024][80] = sum of 16 partials; also emit dt_r bf16 hi/lo.
__global__ void reduce_xp_kernel(float* __restrict__ sp,
                                 const float* __restrict__ part,
                                 __nv_bfloat16* __restrict__ dth,
                                 __nv_bfloat16* __restrict__ dtl)
{
    GRID_SYNC();
    int i = blockIdx.x * blockDim.x + threadIdx.x;
    if (i >= NTOK * SPW) return;
    float s = part[i];
#pragma unroll
    for (int k = 1; k < 16; k++) s += part[i + k * (NTOK * SPW)];
    sp[i] = s;
    int col = i % SPW;
    if (col < DTR) {
        int t = i / SPW;
        __nv_bfloat16 hv = __float2bfloat16(s);
        dth[(size_t)t * DTR + col] = hv;
        dtl[(size_t)t * DTR + col] = __float2bfloat16(s - __bfloat162float(hv));
    }
}

// ---------------------------------------------------------------------------
// Weight fp32 -> bf16 hi/lo conversion (vectorized)
// ---------------------------------------------------------------------------
__global__ void wconv_kernel(const float4* __restrict__ s,
                             __nv_bfloat162* __restrict__ h,
                             __nv_bfloat162* __restrict__ l, int n4)
{
    GRID_SYNC();
    for (int i = blockIdx.x * blockDim.x + threadIdx.x; i < n4;
         i += gridDim.x * blockDim.x) {
        float4 v = s[i];
        __nv_bfloat16 h0 = __float2bfloat16(v.x), h1 = __float2bfloat16(v.y);
        __nv_bfloat16 h2 = __float2bfloat16(v.z), h3 = __float2bfloat16(v.w);
        h[2 * i]     = __nv_bfloat162(h0, h1);
        h[2 * i + 1] = __nv_bfloat162(h2, h3);
        l[2 * i]     = __nv_bfloat162(
            __float2bfloat16(v.x - __bfloat162float(h0)),
            __float2bfloat16(v.y - __bfloat162float(h1)));
        l[2 * i + 1] = __nv_bfloat162(
            __float2bfloat16(v.z - __bfloat162float(h2)),
            __float2bfloat16(v.w - __bfloat162float(h3)));
    }
}

// ---------------------------------------------------------------------------
// Embedding gather
// ---------------------------------------------------------------------------
__global__ void embed_kernel(const int* __restrict__ src,
                             const float* __restrict__ emb,
                             float* __restrict__ h)
{
    int t = blockIdx.x;
    int b = t >> 9, l = t & (LL - 1);
    int id = src[l * BB + b];
    const float* er = emb + (size_t)id * DD;
    float* hr = h + (size_t)t * DD;
    for (int i = threadIdx.x; i < DD; i += 256) hr[i] = er[i];
}

// ---------------------------------------------------------------------------
// RMSNorm -> bf16 hi/lo outputs (layer 0 only)
// ---------------------------------------------------------------------------
__global__ void rmsnorm2_kernel(const float* __restrict__ x,
                                const float* __restrict__ w,
                                __nv_bfloat16* __restrict__ oh,
                                __nv_bfloat16* __restrict__ ol)
{
    GRID_SYNC();
    int t = blockIdx.x;
    const float* xr = x + (size_t)t * DD;
    float s = 0.f;
    for (int i = threadIdx.x; i < DD; i += 256) { float v = xr[i]; s += v * v; }
    __shared__ float red[256];
    red[threadIdx.x] = s;
    __syncthreads();
    for (int off = 128; off > 0; off >>= 1) {
        if (threadIdx.x < off) red[threadIdx.x] += red[threadIdx.x + off];
        __syncthreads();
    }
    float scale = rsqrtf(red[0] / (float)DD + 1e-5f);
    for (int i = threadIdx.x; i < DD; i += 256) {
        float v = xr[i] * scale * w[i];
        __nv_bfloat16 hv = __float2bfloat16(v);
        oh[(size_t)t * DD + i] = hv;
        ol[(size_t)t * DD + i] = __float2bfloat16(v - __bfloat162float(hv));
    }
}

// ---------------------------------------------------------------------------
// Depthwise causal conv (K=4) + SiLU, float4-vectorized over 4 channels,
// reading 3 split-K partials -> bf16 hi/lo
// ---------------------------------------------------------------------------
__global__ void conv_silu_kernel(const float* __restrict__ pin,
                                 const float* __restrict__ cw,
                                 const float* __restrict__ cb,
                                 __nv_bfloat16* __restrict__ uh,
                                 __nv_bfloat16* __restrict__ ul)
{
    GRID_SYNC();
    const size_t P = (size_t)NTOK * 2 * EDD;
    int idx4 = blockIdx.x * blockDim.x + threadIdx.x;
    if (idx4 >= NTOK * EDD / 4) return;
    int idx = idx4 << 2;
    int t = idx / EDD, e = idx - t * EDD;
    int l = t & (LL - 1);

    float4 cbv = *(const float4*)(cb + e);
    float acc[4] = {cbv.x, cbv.y, cbv.z, cbv.w};
    float4 wv[4];
#pragma unroll
    for (int j = 0; j < 4; j++) wv[j] = *(const float4*)(cw + (size_t)(e + j) * KCV);

    const float* base = pin + (size_t)t * (2 * EDD) + e;
#pragma unroll
    for (int tap = 0; tap < 4; tap++) {
        if (l >= 3 - tap) {
            const float* p = base - (3 - tap) * (2 * EDD);
            float4 a = *(const float4*)p;
            float4 b = *(const float4*)(p + P);
            float4 c = *(const float4*)(p + 2 * P);
            acc[0] += (a.x + b.x + c.x) * ((const float*)&wv[0])[tap];
            acc[1] += (a.y + b.y + c.y) * ((const float*)&wv[1])[tap];
            acc[2] += (a.z + b.z + c.z) * ((const float*)&wv[2])[tap];
            acc[3] += (a.w + b.w + c.w) * ((const float*)&wv[3])[tap];
        }
    }

    __nv_bfloat162 hp[2], lp[2];
#pragma unroll
    for (int j = 0; j < 4; j++) {
        float s = 1.f / (1.f + __expf(-acc[j]));
        float v = acc[j] * s;
        __nv_bfloat16 hv = __float2bfloat16(v);
        __nv_bfloat16 lv = __float2bfloat16(v - __bfloat162float(hv));
        if (j & 1) { hp[j >> 1].y = hv; lp[j >> 1].y = lv; }
        else       { hp[j >> 1].x = hv; lp[j >> 1].x = lv; }
    }
    *(__nv_bfloat162*)(uh + idx)     = hp[0];
    *(__nv_bfloat162*)(uh + idx + 2) = hp[1];
    *(__nv_bfloat162*)(ul + idx)     = lp[0];
    *(__nv_bfloat162*)(ul + idx + 2) = lp[1];
}

// ---------------------------------------------------------------------------
// Selective scan: smem-staged 64-step windows, dt pre-activated, bf16 out.
// Gate read directly from the 3 in_proj partials.
// ---------------------------------------------------------------------------
__global__ void __launch_bounds__(128) scan2_kernel(
    const float* __restrict__ dtb,     // [NTOK, ED] softplus-activated
    const __nv_bfloat16* __restrict__ uch,
    const __nv_bfloat16* __restrict__ ucl,
    const float* __restrict__ sp,
    const float* __restrict__ pin,
    const float* __restrict__ A_log,
    const float* __restrict__ Dp,
    __nv_bfloat16* __restrict__ yh,
    __nv_bfloat16* __restrict__ yl)
{
    GRID_SYNC();
    __shared__ float  sdt[64][32], suc[64][32], sg[64][32];
    __shared__ float4 sB[64][4], sC[64][4];

    const size_t P = (size_t)NTOK * 2 * EDD;
    const int b  = blockIdx.y;
    const int eb = blockIdx.x * 32;
    const int tid = threadIdx.x;
    const int q = tid & 3, er = tid >> 2;
    const int e = eb + er;

    float4 al = *(const float4*)(A_log + (size_t)e * NST + q * 4);
    float a0 = -__expf(al.x), a1 = -__expf(al.y),
          a2 = -__expf(al.z), a3 = -__expf(al.w);
    const float dD = Dp[e];

    float h0 = 0.f, h1 = 0.f, h2 = 0.f, h3 = 0.f;

    for (int w = 0; w < 8; w++) {
        const int t0 = b * LL + w * 64;
#pragma unroll
        for (int i = 0; i < 16; i++) {
            int idx = tid + i * 128;
            int s = idx >> 5, j = idx & 31;
            size_t tr = (size_t)(t0 + s);
            sdt[s][j] = dtb[tr * EDD + eb + j];
            suc[s][j] = __bfloat162float(uch[tr * EDD + eb + j])
                      + __bfloat162float(ucl[tr * EDD + eb + j]);
            const float* gp = pin + tr * (2 * EDD) + EDD + eb + j;
            sg[s][j] = gp[0] + gp[P] + gp[2 * P];
            float v = sp[tr * SPW + DTR + j];
            if (j < 16) ((float*)&sB[s][0])[j]      = v;
            else        ((float*)&sC[s][0])[j - 16] = v;
        }
        __syncthreads();
#pragma unroll 4
        for (int s = 0; s < 64; s++) {
            float dtv = sdt[s][er];
            float u = suc[s][er];
            float4 Bv = sB[s][q], Cv = sC[s][q];
            float du = dtv * u;
            h0 = __expf(dtv * a0) * h0 + du * Bv.x;
            h1 = __expf(dtv * a1) * h1 + du * Bv.y;
            h2 = __expf(dtv * a2) * h2 + du * Bv.z;
            h3 = __expf(dtv * a3) * h3 + du * Bv.w;
            float ys = h0 * Cv.x + h1 * Cv.y + h2 * Cv.z + h3 * Cv.w;
            ys += __shfl_xor_sync(0xffffffffu, ys, 1);
            ys += __shfl_xor_sync(0xffffffffu, ys, 2);
            if (q == 0) {
                float gv = sg[s][er];
                float yv = (ys + u * dD) * (gv / (1.f + __expf(-gv)));
                __nv_bfloat16 hv = __float2bfloat16(yv);
                size_t o = (size_t)(t0 + s) * EDD + e;
                yh[o] = hv;
                yl[o] = __float2bfloat16(yv - __bfloat162float(hv));
            }
        }
        __syncthreads();
    }
}

// ---------------------------------------------------------------------------
// PDL launch helper: every launch carries programmatic-stream-serialization.
// ---------------------------------------------------------------------------
static cudaLaunchAttribute g_pdl_attr[1];

static cudaLaunchConfig_t pdl_cfg(dim3 grid, dim3 block, size_t smem) {
    g_pdl_attr[0].id = cudaLaunchAttributeProgrammaticStreamSerialization;
    g_pdl_attr[0].val.programmaticStreamSerializationAllowed = 1;
    cudaLaunchConfig_t c;
    c.gridDim = grid; c.blockDim = block; c.dynamicSmemBytes = smem;
    c.stream = 0; c.attrs = g_pdl_attr; c.numAttrs = 1;
    return c;
}

// ---------------------------------------------------------------------------
extern "C" void kernel_launch(void* const* d_in, const int* in_sizes, int n_in,
                              void* d_out, int out_size)
{
    const int*   src     = (const int*)  d_in[0];
    const float* emb     = (const float*)d_in[1];
    const float* norm_w  = (const float*)d_in[2];
    const float* in_proj = (const float*)d_in[3];
    const float* conv_w  = (const float*)d_in[4];
    const float* conv_b  = (const float*)d_in[5];
    const float* x_proj  = (const float*)d_in[6];
    const float* dt_w    = (const float*)d_in[7];
    const float* dt_b    = (const float*)d_in[8];
    const float* A_log   = (const float*)d_in[9];
    const float* Dp      = (const float*)d_in[10];
    const float* out_prj = (const float*)d_in[11];
    const float* normf_w = (const float*)d_in[12];
    float* out = (float*)d_out;
    (void)in_sizes; (void)n_in; (void)out_size;

    cudaFuncSetAttribute(gemm_mma,
                         cudaFuncAttributeMaxDynamicSharedMemorySize, GEMM_SMEM);

    float *h, *sp, *dtb, *pin, *pxp, *pout;
    __nv_bfloat16 *xnh, *xnl, *uch, *ucl, *dth, *dtl, *yh, *yl;
    __nv_bfloat16 *wih, *wil, *wxh, *wxl, *wdh, *wdl, *woh, *wol, *weh, *wel;
    cudaGetSymbolAddress((void**)&h,    g_h);
    cudaGetSymbolAddress((void**)&sp,   g_sp);
    cudaGetSymbolAddress((void**)&dtb,  g_dtb);
    cudaGetSymbolAddress((void**)&pin,  g_pin);
    cudaGetSymbolAddress((void**)&pxp,  g_pxp);
    cudaGetSymbolAddress((void**)&pout, g_pout);
    cudaGetSymbolAddress((void**)&xnh, g_xnh);
    cudaGetSymbolAddress((void**)&xnl, g_xnl);
    cudaGetSymbolAddress((void**)&uch, g_uch);
    cudaGetSymbolAddress((void**)&ucl, g_ucl);
    cudaGetSymbolAddress((void**)&dth, g_dth);
    cudaGetSymbolAddress((void**)&dtl, g_dtl);
    cudaGetSymbolAddress((void**)&yh,  g_yh);
    cudaGetSymbolAddress((void**)&yl,  g_yl);
    cudaGetSymbolAddress((void**)&wih, g_wih);
    cudaGetSymbolAddress((void**)&wil, g_wil);
    cudaGetSymbolAddress((void**)&wxh, g_wxh);
    cudaGetSymbolAddress((void**)&wxl, g_wxl);
    cudaGetSymbolAddress((void**)&wdh, g_wdh);
    cudaGetSymbolAddress((void**)&wdl, g_wdl);
    cudaGetSymbolAddress((void**)&woh, g_woh);
    cudaGetSymbolAddress((void**)&wol, g_wol);
    cudaGetSymbolAddress((void**)&weh, g_weh);
    cudaGetSymbolAddress((void**)&wel, g_wel);

    const dim3 gIn (2 * EDD / 128, NTOK / 128, 3);   // N=3072, klen 256
    const dim3 gXp (1,             NTOK / 128, 16);  // N=80,   klen 96
    const dim3 gDt (EDD / 128,     NTOK / 128, 1);   // N=1536, K=48
    const dim3 gOut(DD / 128,      NTOK / 128, 3);   // N=768,  klen 512
    const dim3 gLog(VV / 128,      NTOK / 128, 2);   // N=1024, klen 384
    const dim3 gScan(EDD / 32, BB);

    const float* nullb = (const float*)0;

    // Launch order: my launch #4 is the in_proj GEMM (profiled by ncu -s5).
    {
        cudaLaunchConfig_t c = pdl_cfg(dim3(NTOK), dim3(256), 0);               // 1
        cudaLaunchKernelEx(&c, embed_kernel, src, emb, h);
    }
    {
        cudaLaunchConfig_t c = pdl_cfg(dim3(2048), dim3(256), 0);               // 2
        cudaLaunchKernelEx(&c, wconv_kernel, (const float4*)in_proj,
            (__nv_bfloat162*)wih, (__nv_bfloat162*)wil, NLAY * 2 * EDD * DD / 4);
    }
    {
        cudaLaunchConfig_t c = pdl_cfg(dim3(NTOK), dim3(256), 0);               // 3
        cudaLaunchKernelEx(&c, rmsnorm2_kernel, (const float*)h, norm_w, xnh, xnl);
    }

    for (int lay = 0; lay < NLAY; lay++) {
        {
            cudaLaunchConfig_t c = pdl_cfg(gIn, dim3(256), GEMM_SMEM);          // 4 <- profiled
            cudaLaunchKernelEx(&c, gemm_mma,
                (const __nv_bfloat16*)xnh, (const __nv_bfloat16*)xnl, DD,
                (const __nv_bfloat16*)(wih + (size_t)lay * 2 * EDD * DD),
                (const __nv_bfloat16*)(wil + (size_t)lay * 2 * EDD * DD), DD,
                pin, nullb, 2 * EDD, DD, 3, 256);
        }
        if (lay == 0) {
            cudaLaunchConfig_t c1 = pdl_cfg(dim3(1024), dim3(256), 0);
            cudaLaunchKernelEx(&c1, wconv_kernel, (const float4*)x_proj,
                (__nv_bfloat162*)wxh, (__nv_bfloat162*)wxl, NLAY * SPW * EDD / 4);
            cudaLaunchConfig_t c2 = pdl_cfg(dim3(1024), dim3(256), 0);
            cudaLaunchKernelEx(&c2, wconv_kernel, (const float4*)dt_w,
                (__nv_bfloat162*)wdh, (__nv_bfloat162*)wdl, NLAY * EDD * DTR / 4);
            cudaLaunchConfig_t c3 = pdl_cfg(dim3(2048), dim3(256), 0);
            cudaLaunchKernelEx(&c3, wconv_kernel, (const float4*)out_prj,
                (__nv_bfloat162*)woh, (__nv_bfloat162*)wol, NLAY * DD * EDD / 4);
            cudaLaunchConfig_t c4 = pdl_cfg(dim3(1024), dim3(256), 0);
            cudaLaunchKernelEx(&c4, wconv_kernel, (const float4*)emb,
                (__nv_bfloat162*)weh, (__nv_bfloat162*)wel, VV * DD / 4);
        }
        {
            cudaLaunchConfig_t c = pdl_cfg(dim3((NTOK * EDD / 4) / 256), dim3(256), 0);
            cudaLaunchKernelEx(&c, conv_silu_kernel, (const float*)pin,
                (const float*)(conv_w + (size_t)lay * EDD * KCV),
                (const float*)(conv_b + (size_t)lay * EDD), uch, ucl);
        }
        {
            cudaLaunchConfig_t c = pdl_cfg(gXp, dim3(256), GEMM_SMEM);
            cudaLaunchKernelEx(&c, gemm_mma,
                (const __nv_bfloat16*)uch, (const __nv_bfloat16*)ucl, EDD,
                (const __nv_bfloat16*)(wxh + (size_t)lay * SPW * EDD),
                (const __nv_bfloat16*)(wxl + (size_t)lay * SPW * EDD), EDD,
                pxp, nullb, SPW, EDD, 3, 96);
        }
        {
            cudaLaunchConfig_t c = pdl_cfg(dim3((NTOK * SPW + 255) / 256), dim3(256), 0);
            cudaLaunchKernelEx(&c, reduce_xp_kernel, sp, (const float*)pxp, dth, dtl);
        }
        {
            cudaLaunchConfig_t c = pdl_cfg(gDt, dim3(256), GEMM_SMEM);
            cudaLaunchKernelEx(&c, gemm_mma,
                (const __nv_bfloat16*)dth, (const __nv_bfloat16*)dtl, DTR,
                (const __nv_bfloat16*)(wdh + (size_t)lay * EDD * DTR),
                (const __nv_bfloat16*)(wdl + (size_t)lay * EDD * DTR), DTR,
                dtb, (const float*)(dt_b + (size_t)lay * EDD), EDD, DTR, 4, 64);
        }
        {
            cudaLaunchConfig_t c = pdl_cfg(gScan, dim3(128), 0);
            cudaLaunchKernelEx(&c, scan2_kernel,
                (const float*)dtb, (const __nv_bfloat16*)uch, (const __nv_bfloat16*)ucl,
                (const float*)sp, (const float*)pin,
                (const float*)(A_log + (size_t)lay * EDD * NST),
                (const float*)(Dp + (size_t)lay * EDD), yh, yl);
        }
        {
            cudaLaunchConfig_t c = pdl_cfg(gOut, dim3(256), GEMM_SMEM);
            cudaLaunchKernelEx(&c, gemm_mma,
                (const __nv_bfloat16*)yh, (const __nv_bfloat16*)yl, EDD,
                (const __nv_bfloat16*)(woh + (size_t)lay * DD * EDD),
                (const __nv_bfloat16*)(wol + (size_t)lay * DD * EDD), EDD,
                pout, nullb, DD, EDD, 3, 512);
        }
        {
            cudaLaunchConfig_t c = pdl_cfg(dim3(NTOK), dim3(256), 0);
            cudaLaunchKernelEx(&c, reduce_rms_kernel, h, (const float*)pout,
                (const float*)((lay + 1 < NLAY) ? (norm_w + (size_t)(lay + 1) * DD)
                                                : normf_w),
                xnh, xnl);
        }
    }

    {
        cudaLaunchConfig_t c = pdl_cfg(gLog, dim3(256), GEMM_SMEM);
        cudaLaunchKernelEx(&c, gemm_mma,
            (const __nv_bfloat16*)xnh, (const __nv_bfloat16*)xnl, DD,
            (const __nv_bfloat16*)weh, (const __nv_bfloat16*)wel, DD,
            pout, nullb, VV, DD, 3, 384);
    }
    {
        cudaLaunchConfig_t c = pdl_cfg(dim3((NTOK * VV / 4 + 255) / 256), dim3(256), 0);
        cudaLaunchKernelEx(&c, reduce_kernel, out, (const float*)pout,
                           NTOK * VV / 4, NTOK * VV / 4, 2);
    }
}